// round 5
// baseline (speedup 1.0000x reference)
#include <cuda_runtime.h>
#include <cuda_bf16.h>

#define NKER 25
#define HP   8        // padded inner dim (6 feats + basis-sum + pad)
#define HROW 200      // NKER * HP floats per node
#define HW   150      // logical 25*6
#define JD   156      // 150 + 6 (H rows + x rows)
#define CD   78       // 75 Z cols + 3 root cols
#define GH   13       // column groups per block-half
#define NMAX 50000
#define EMAX 1600000

// scratch (no cudaMalloc allowed)
__device__ float  g_H[NMAX * HROW];     // 40 MB, [n][k][8]: 6 feats, slot6=Σbasis(deg), slot7 pad
__device__ float  g_inv[NMAX];
__device__ float4 g_X8[NMAX * 2];       // x packed 32B-aligned: {x0..x5,0,0}
__device__ float4 g_Z4[NMAX * NKER];    // 20 MB, (z0,z1,z2,pad) per (n,kk)
__device__ float4 g_A4[NMAX];           // edge-2 accumulator
__device__ float  g_M[JD * CD];         // fused weight matrix

// ---------------------------------------------------------------------------
__global__ void k_zero(const float* __restrict__ x, int N) {
    int i = blockIdx.x * blockDim.x + threadIdx.x;
    int stride = gridDim.x * blockDim.x;
    float4 z4 = make_float4(0.f, 0.f, 0.f, 0.f);
    float4* H4 = reinterpret_cast<float4*>(g_H);
    int nH4 = N * (HROW / 4);
    for (int t = i; t < nH4; t += stride) H4[t] = z4;
    for (int t = i; t < N; t += stride) {
        g_A4[t] = z4;
        const float2* x2 = reinterpret_cast<const float2*>(x) + t * 3;
        float2 xa = x2[0], xb = x2[1], xc = x2[2];
        g_X8[2 * t]     = make_float4(xa.x, xa.y, xb.x, xb.y);
        g_X8[2 * t + 1] = make_float4(xc.x, xc.y, 0.f, 0.f);
    }
}

// degree-1 open B-spline, K=5: 4 corners
__device__ __forceinline__ void spline4(float p0, float p1, float* b, int* id) {
    float v0 = p0 * 4.0f, v1 = p1 * 4.0f;
    float fl0 = floorf(v0), fl1 = floorf(v1);
    int i0 = (int)fl0, i1 = (int)fl1;
    i0 = min(max(i0, 0), 3);
    i1 = min(max(i1, 0), 3);
    float f0 = v0 - fl0, f1 = v1 - fl1;
    float g0 = 1.0f - f0, g1 = 1.0f - f1;
    b[0] = g0 * g1; b[1] = f0 * g1; b[2] = g0 * f1; b[3] = f0 * f1;
    int base = i0 + 5 * i1;
    id[0] = base; id[1] = base + 1; id[2] = base + 5; id[3] = base + 6;
}

// ---------------------------------------------------------------------------
// Edge pass 1: H[dst, idx_s, 0:6] += basis_s * x[src, :]; slot6 += basis_s
__global__ void k_edge1(const int* __restrict__ ei, const float* __restrict__ ps,
                        int E) {
    int e = blockIdx.x * blockDim.x + threadIdx.x;
    if (e >= E) return;
    int dst = ei[e];
    int src = ei[E + e];
    float2 p = reinterpret_cast<const float2*>(ps)[e];
    float b[4]; int id[4];
    spline4(p.x, p.y, b, id);
    float4 xa = __ldg(g_X8 + 2 * src);
    float4 xb = __ldg(g_X8 + 2 * src + 1);
    float4* Hd = reinterpret_cast<float4*>(g_H + (size_t)dst * HROW);
#pragma unroll
    for (int s = 0; s < 4; s++) {
        float bs = b[s];
        float4* hp = Hd + id[s] * 2;
        atomicAdd(hp,     make_float4(bs * xa.x, bs * xa.y, bs * xa.z, bs * xa.w));
        atomicAdd(hp + 1, make_float4(bs * xb.x, bs * xb.y, bs, 0.f));
    }
}

// ---------------------------------------------------------------------------
// Build fused M (156 x 78). Block j; 4 i-slices per col, smem reduce.
__global__ void k_buildM(const float* __restrict__ w, const float* __restrict__ rw,
                         const float* __restrict__ w1, const float* __restrict__ rw1) {
    __shared__ float sA[1024];
    __shared__ float red[CD][4];
    int j = blockIdx.x;
    int tid = threadIdx.x;
    const float* Arow = (j < HW) ? (w + (j / 6) * 6144 + (j % 6) * 1024)
                                 : (rw + (j - HW) * 1024);
    for (int i = tid; i < 1024; i += blockDim.x) sA[i] = Arow[i];
    __syncthreads();
    int c = tid >> 2, sl = tid & 3;
    if (c < CD) {
        const float* Bp = (c < 75) ? (w1 + (c / 3) * 3072 + (c % 3)) : (rw1 + (c - 75));
        float acc = 0.f;
        int i0 = sl * 256;
#pragma unroll 8
        for (int i = i0; i < i0 + 256; i++) acc = fmaf(sA[i], __ldg(Bp + i * 3), acc);
        red[c][sl] = acc;
    }
    __syncthreads();
    if (tid < CD)
        g_M[j * CD + tid] = (red[tid][0] + red[tid][1]) + (red[tid][2] + red[tid][3]);
}

// ---------------------------------------------------------------------------
// Z GEMM, column-split: blockIdx.y = half (13 groups of 3 cols each).
// One thread = one node x 13 groups. Per j: 13 LDS.128 + 39 FMA.
__global__ void __launch_bounds__(128, 6)
k_zgemm(float* __restrict__ dout, int N) {
    __shared__ float4 sB[JD * GH];   // 156*13*16 = 32448 B
    int tid = threadIdx.x;
    int half = blockIdx.y;
    int g0 = half * GH;

    for (int idx = tid; idx < JD * GH; idx += 128) {
        int j = idx / GH, g = idx - j * GH;
        int c = 3 * (g0 + g);
        const float* m = g_M + j * CD + c;
        sB[idx] = make_float4(m[0], m[1], m[2], 0.f);
    }
    __syncthreads();

    int n = blockIdx.x * 128 + tid;
    if (n >= N) return;

    float ax[GH], ay[GH], az[GH];
#pragma unroll
    for (int g = 0; g < GH; g++) { ax[g] = 0.f; ay[g] = 0.f; az[g] = 0.f; }

    const float4* H4 = reinterpret_cast<const float4*>(g_H + (size_t)n * HROW);
    float d = 0.f;

    for (int k = 0; k < NKER; k++) {
        float4 h0 = __ldg(H4 + 2 * k);
        float4 h1 = __ldg(H4 + 2 * k + 1);
        d += h1.z;
        float av[6] = {h0.x, h0.y, h0.z, h0.w, h1.x, h1.y};
#pragma unroll
        for (int i = 0; i < 6; i++) {
            float a = av[i];
            const float4* bj = sB + (k * 6 + i) * GH;
#pragma unroll
            for (int g = 0; g < GH; g++) {
                float4 b = bj[g];
                ax[g] = fmaf(a, b.x, ax[g]);
                ay[g] = fmaf(a, b.y, ay[g]);
                az[g] = fmaf(a, b.z, az[g]);
            }
        }
    }

    float inv = 1.0f / fmaxf(d, 1.0f);
    if (half == 0) g_inv[n] = inv;
#pragma unroll
    for (int g = 0; g < GH; g++) { ax[g] *= inv; ay[g] *= inv; az[g] *= inv; }

    // x part (rows 150..155), unscaled
    float4 xa = __ldg(g_X8 + 2 * n);
    float4 xb = __ldg(g_X8 + 2 * n + 1);
    float xv[6] = {xa.x, xa.y, xa.z, xa.w, xb.x, xb.y};
#pragma unroll
    for (int i = 0; i < 6; i++) {
        float a = xv[i];
        const float4* bj = sB + (HW + i) * GH;
#pragma unroll
        for (int g = 0; g < GH; g++) {
            float4 b = bj[g];
            ax[g] = fmaf(a, b.x, ax[g]);
            ay[g] = fmaf(a, b.y, ay[g]);
            az[g] = fmaf(a, b.z, az[g]);
        }
    }

    float4* Zn = g_Z4 + (size_t)n * NKER;
    if (half == 0) {
#pragma unroll
        for (int g = 0; g < GH; g++)
            Zn[g] = make_float4(ax[g], ay[g], az[g], 0.f);
    } else {
#pragma unroll
        for (int g = 0; g < GH - 1; g++)
            Zn[13 + g] = make_float4(ax[g], ay[g], az[g], 0.f);
        dout[n * 3 + 0] = ax[GH - 1];
        dout[n * 3 + 1] = ay[GH - 1];
        dout[n * 3 + 2] = az[GH - 1];
    }
}

// ---------------------------------------------------------------------------
// Edge pass 2: A4[dst] += sum_s basis1_s * Z[src, idx_s, :]  (one float4 atomic)
__global__ void k_edge2(const int* __restrict__ ei, const float* __restrict__ ps,
                        int E) {
    int e = blockIdx.x * blockDim.x + threadIdx.x;
    if (e >= E) return;
    int dst = ei[e];
    int src = ei[E + e];
    float2 p = reinterpret_cast<const float2*>(ps)[e];
    float b[4]; int id[4];
    spline4(p.x, p.y, b, id);
    const float4* Z = g_Z4 + (size_t)src * NKER;
    float a0 = 0.f, a1 = 0.f, a2 = 0.f;
#pragma unroll
    for (int s = 0; s < 4; s++) {
        float4 z = __ldg(Z + id[s]);
        a0 = fmaf(b[s], z.x, a0);
        a1 = fmaf(b[s], z.y, a1);
        a2 = fmaf(b[s], z.z, a2);
    }
    atomicAdd(g_A4 + dst, make_float4(a0, a1, a2, 0.f));
}

// ---------------------------------------------------------------------------
// Final: out[n] = root_term (already in dout) + inv[n] * A4[n]
__global__ void k_final(float* __restrict__ dout, int N) {
    int n = blockIdx.x * blockDim.x + threadIdx.x;
    if (n >= N) return;
    float4 a = g_A4[n];
    float inv = g_inv[n];
    dout[n * 3 + 0] += a.x * inv;
    dout[n * 3 + 1] += a.y * inv;
    dout[n * 3 + 2] += a.z * inv;
}

// ---------------------------------------------------------------------------
extern "C" void kernel_launch(void* const* d_in, const int* in_sizes, int n_in,
                              void* d_out, int out_size) {
    const float* x   = (const float*)d_in[0];
    const int*   ei  = (const int*)d_in[1];
    const float* ps  = (const float*)d_in[2];
    const float* ps1 = (const float*)d_in[3];
    const float* w   = (const float*)d_in[4];
    const float* rw  = (const float*)d_in[5];
    const float* w1  = (const float*)d_in[6];
    const float* rw1 = (const float*)d_in[7];
    float* dout = (float*)d_out;

    int N = in_sizes[0] / 6;
    int E = in_sizes[2] / 2;
    if (N > NMAX) N = NMAX;
    if (E > EMAX) E = EMAX;

    k_zero<<<2048, 256>>>(x, N);
    k_edge1<<<(E + 255) / 256, 256>>>(ei, ps, E);
    k_buildM<<<JD, 320>>>(w, rw, w1, rw1);

    dim3 gz((N + 127) / 128, 2);
    k_zgemm<<<gz, 128>>>(dout, N);

    k_edge2<<<(E + 255) / 256, 256>>>(ei, ps1, E);
    k_final<<<(N + 255) / 256, 256>>>(dout, N);
}

// round 6
// speedup vs baseline: 1.1627x; 1.1627x over previous
#include <cuda_runtime.h>
#include <cuda_bf16.h>

#define NKER 25
#define HP   8        // padded inner dim (6 feats + basis-sum + pad)
#define HROW 200      // NKER * HP floats per node
#define HW   150      // logical 25*6
#define JD   156      // 150 + 6 (H rows + x rows)
#define CD   78       // 75 Z cols + 3 root cols
#define MP   80       // sM pitch (floats), cols 78,79 zero
#define CK   5        // kernels per staged chunk
#define SP   41       // staging pitch in floats (conflict-free: 41 mod 32 = 9)
#define NMAX 50000
#define EMAX 1600000

// scratch (no cudaMalloc allowed)
__device__ float  g_H[NMAX * HROW];     // 40 MB, [n][k][8]: 6 feats, slot6=Σbasis(deg), slot7 pad
__device__ float  g_inv[NMAX];
__device__ float4 g_X8[NMAX * 2];       // x packed 32B-aligned: {x0..x5,0,0}
__device__ float4 g_Z4[NMAX * NKER];    // 20 MB, (z0,z1,z2,pad) per (n,kk)
__device__ float4 g_A4[NMAX];           // edge-2 accumulator
__device__ float  g_M[JD * CD];         // fused weight matrix

// ---------------------------------------------------------------------------
__global__ void k_zero(const float* __restrict__ x, int N) {
    int i = blockIdx.x * blockDim.x + threadIdx.x;
    int stride = gridDim.x * blockDim.x;
    float4 z4 = make_float4(0.f, 0.f, 0.f, 0.f);
    float4* H4 = reinterpret_cast<float4*>(g_H);
    int nH4 = N * (HROW / 4);
    for (int t = i; t < nH4; t += stride) H4[t] = z4;
    for (int t = i; t < N; t += stride) {
        g_A4[t] = z4;
        const float2* x2 = reinterpret_cast<const float2*>(x) + t * 3;
        float2 xa = x2[0], xb = x2[1], xc = x2[2];
        g_X8[2 * t]     = make_float4(xa.x, xa.y, xb.x, xb.y);
        g_X8[2 * t + 1] = make_float4(xc.x, xc.y, 0.f, 0.f);
    }
}

// degree-1 open B-spline, K=5: 4 corners
__device__ __forceinline__ void spline4(float p0, float p1, float* b, int* id) {
    float v0 = p0 * 4.0f, v1 = p1 * 4.0f;
    float fl0 = floorf(v0), fl1 = floorf(v1);
    int i0 = (int)fl0, i1 = (int)fl1;
    i0 = min(max(i0, 0), 3);
    i1 = min(max(i1, 0), 3);
    float f0 = v0 - fl0, f1 = v1 - fl1;
    float g0 = 1.0f - f0, g1 = 1.0f - f1;
    b[0] = g0 * g1; b[1] = f0 * g1; b[2] = g0 * f1; b[3] = f0 * f1;
    int base = i0 + 5 * i1;
    id[0] = base; id[1] = base + 1; id[2] = base + 5; id[3] = base + 6;
}

// ---------------------------------------------------------------------------
// Edge pass 1: H[dst, idx_s, 0:6] += basis_s * x[src, :]; slot6 += basis_s
__global__ void k_edge1(const int* __restrict__ ei, const float* __restrict__ ps,
                        int E) {
    int e = blockIdx.x * blockDim.x + threadIdx.x;
    if (e >= E) return;
    int dst = ei[e];
    int src = ei[E + e];
    float2 p = reinterpret_cast<const float2*>(ps)[e];
    float b[4]; int id[4];
    spline4(p.x, p.y, b, id);
    float4 xa = __ldg(g_X8 + 2 * src);
    float4 xb = __ldg(g_X8 + 2 * src + 1);
    float4* Hd = reinterpret_cast<float4*>(g_H + (size_t)dst * HROW);
#pragma unroll
    for (int s = 0; s < 4; s++) {
        float bs = b[s];
        float4* hp = Hd + id[s] * 2;
        atomicAdd(hp,     make_float4(bs * xa.x, bs * xa.y, bs * xa.z, bs * xa.w));
        atomicAdd(hp + 1, make_float4(bs * xb.x, bs * xb.y, bs, 0.f));
    }
}

// ---------------------------------------------------------------------------
// Build fused M (156 x 78). Block j; 4 i-slices per col, smem reduce.
__global__ void k_buildM(const float* __restrict__ w, const float* __restrict__ rw,
                         const float* __restrict__ w1, const float* __restrict__ rw1) {
    __shared__ float sA[1024];
    __shared__ float red[CD][4];
    int j = blockIdx.x;
    int tid = threadIdx.x;
    const float* Arow = (j < HW) ? (w + (j / 6) * 6144 + (j % 6) * 1024)
                                 : (rw + (j - HW) * 1024);
    for (int i = tid; i < 1024; i += blockDim.x) sA[i] = Arow[i];
    __syncthreads();
    int c = tid >> 2, sl = tid & 3;
    if (c < CD) {
        const float* Bp = (c < 75) ? (w1 + (c / 3) * 3072 + (c % 3)) : (rw1 + (c - 75));
        float acc = 0.f;
        int i0 = sl * 256;
#pragma unroll 8
        for (int i = i0; i < i0 + 256; i++) acc = fmaf(sA[i], __ldg(Bp + i * 3), acc);
        red[c][sl] = acc;
    }
    __syncthreads();
    if (tid < CD)
        g_M[j * CD + tid] = (red[tid][0] + red[tid][1]) + (red[tid][2] + red[tid][3]);
}

// ---------------------------------------------------------------------------
// Z GEMM: one thread = one node; all 78 cols in registers.
// H staged through smem in 5 chunks of 5 kernels (coalesced LDG, conflict-free LDS).
__global__ void __launch_bounds__(128, 3)
k_zgemm(float* __restrict__ dout, int N) {
    extern __shared__ float sm[];
    float* sM = sm;                    // JD*MP = 12480 floats (49920 B)
    float* sH = sm + JD * MP;          // 128*SP = 5248 floats (20992 B)
    int tid = threadIdx.x;
    int n0 = blockIdx.x * 128;
    int n = n0 + tid;

    for (int idx = tid; idx < JD * MP; idx += 128) {
        int j = idx / MP, c = idx - j * MP;
        sM[idx] = (c < CD) ? g_M[j * CD + c] : 0.f;
    }

    float acc[80];
#pragma unroll
    for (int c = 0; c < 80; c++) acc[c] = 0.f;
    float d = 0.f;

    const float4* H4base = reinterpret_cast<const float4*>(g_H);

    for (int ch = 0; ch < NKER / CK; ch++) {
        __syncthreads();   // previous chunk fully consumed / sM ready on first iter
        // stage: 128 nodes x 10 float4 (kernels 5ch..5ch+4), coalesced
        for (int idx = tid; idx < 128 * 10; idx += 128) {
            int r = idx / 10, q = idx - r * 10;
            int nn = n0 + r;
            float4 v = make_float4(0.f, 0.f, 0.f, 0.f);
            if (nn < N) v = __ldg(H4base + (size_t)nn * (HROW / 4) + ch * 10 + q);
            float* dstp = sH + r * SP + q * 4;
            dstp[0] = v.x; dstp[1] = v.y; dstp[2] = v.z; dstp[3] = v.w;
        }
        __syncthreads();

        if (n < N) {
            const float* my = sH + tid * SP;
#pragma unroll
            for (int k = 0; k < CK; k++) {
                const float* hk = my + k * 8;
                d += hk[6];
                int jb = (ch * CK + k) * 6;
#pragma unroll
                for (int i = 0; i < 6; i++) {
                    float a = hk[i];
                    const float4* m4 = reinterpret_cast<const float4*>(sM + (jb + i) * MP);
#pragma unroll
                    for (int g = 0; g < 20; g++) {
                        float4 b = m4[g];
                        acc[4 * g + 0] = fmaf(a, b.x, acc[4 * g + 0]);
                        acc[4 * g + 1] = fmaf(a, b.y, acc[4 * g + 1]);
                        acc[4 * g + 2] = fmaf(a, b.z, acc[4 * g + 2]);
                        acc[4 * g + 3] = fmaf(a, b.w, acc[4 * g + 3]);
                    }
                }
            }
        }
    }

    if (n >= N) return;

    float inv = 1.0f / fmaxf(d, 1.0f);
    g_inv[n] = inv;
#pragma unroll
    for (int c = 0; c < 80; c++) acc[c] *= inv;

    // x part (rows 150..155 of M), unscaled
    float4 xa = __ldg(g_X8 + 2 * n);
    float4 xb = __ldg(g_X8 + 2 * n + 1);
    float xv[6] = {xa.x, xa.y, xa.z, xa.w, xb.x, xb.y};
#pragma unroll
    for (int i = 0; i < 6; i++) {
        float a = xv[i];
        const float4* m4 = reinterpret_cast<const float4*>(sM + (HW + i) * MP);
#pragma unroll
        for (int g = 0; g < 20; g++) {
            float4 b = m4[g];
            acc[4 * g + 0] = fmaf(a, b.x, acc[4 * g + 0]);
            acc[4 * g + 1] = fmaf(a, b.y, acc[4 * g + 1]);
            acc[4 * g + 2] = fmaf(a, b.z, acc[4 * g + 2]);
            acc[4 * g + 3] = fmaf(a, b.w, acc[4 * g + 3]);
        }
    }

    float4* Zn = g_Z4 + (size_t)n * NKER;
#pragma unroll
    for (int kk = 0; kk < NKER; kk++)
        Zn[kk] = make_float4(acc[3 * kk], acc[3 * kk + 1], acc[3 * kk + 2], 0.f);
    dout[n * 3 + 0] = acc[75];
    dout[n * 3 + 1] = acc[76];
    dout[n * 3 + 2] = acc[77];
}

// ---------------------------------------------------------------------------
// Edge pass 2: A4[dst] += sum_s basis1_s * Z[src, idx_s, :]  (one float4 atomic)
__global__ void k_edge2(const int* __restrict__ ei, const float* __restrict__ ps,
                        int E) {
    int e = blockIdx.x * blockDim.x + threadIdx.x;
    if (e >= E) return;
    int dst = ei[e];
    int src = ei[E + e];
    float2 p = reinterpret_cast<const float2*>(ps)[e];
    float b[4]; int id[4];
    spline4(p.x, p.y, b, id);
    const float4* Z = g_Z4 + (size_t)src * NKER;
    float a0 = 0.f, a1 = 0.f, a2 = 0.f;
#pragma unroll
    for (int s = 0; s < 4; s++) {
        float4 z = __ldg(Z + id[s]);
        a0 = fmaf(b[s], z.x, a0);
        a1 = fmaf(b[s], z.y, a1);
        a2 = fmaf(b[s], z.z, a2);
    }
    atomicAdd(g_A4 + dst, make_float4(a0, a1, a2, 0.f));
}

// ---------------------------------------------------------------------------
// Final: out[n] = root_term (already in dout) + inv[n] * A4[n]
__global__ void k_final(float* __restrict__ dout, int N) {
    int n = blockIdx.x * blockDim.x + threadIdx.x;
    if (n >= N) return;
    float4 a = g_A4[n];
    float inv = g_inv[n];
    dout[n * 3 + 0] += a.x * inv;
    dout[n * 3 + 1] += a.y * inv;
    dout[n * 3 + 2] += a.z * inv;
}

// ---------------------------------------------------------------------------
extern "C" void kernel_launch(void* const* d_in, const int* in_sizes, int n_in,
                              void* d_out, int out_size) {
    const float* x   = (const float*)d_in[0];
    const int*   ei  = (const int*)d_in[1];
    const float* ps  = (const float*)d_in[2];
    const float* ps1 = (const float*)d_in[3];
    const float* w   = (const float*)d_in[4];
    const float* rw  = (const float*)d_in[5];
    const float* w1  = (const float*)d_in[6];
    const float* rw1 = (const float*)d_in[7];
    float* dout = (float*)d_out;

    int N = in_sizes[0] / 6;
    int E = in_sizes[2] / 2;
    if (N > NMAX) N = NMAX;
    if (E > EMAX) E = EMAX;

    k_zero<<<2048, 256>>>(x, N);
    k_edge1<<<(E + 255) / 256, 256>>>(ei, ps, E);
    k_buildM<<<JD, 320>>>(w, rw, w1, rw1);

    size_t smemC = (size_t)(JD * MP + 128 * SP) * sizeof(float);   // 70912 B
    cudaFuncSetAttribute(k_zgemm, cudaFuncAttributeMaxDynamicSharedMemorySize, (int)smemC);
    k_zgemm<<<(N + 127) / 128, 128, smemC>>>(dout, N);

    k_edge2<<<(E + 255) / 256, 256>>>(ei, ps1, E);
    k_final<<<(N + 255) / 256, 256>>>(dout, N);
}